// round 6
// baseline (speedup 1.0000x reference)
#include <cuda_runtime.h>
#include <cstdint>

#define S_LEN 4096
#define CCH   512
#define NH    8
#define DH    64
#define BATCH 2

// Scratch (allocation-free contract: __device__ globals)
__device__ float g_q[(size_t)BATCH * NH * S_LEN * DH];       // [b*8+h][s][d], pre-scaled by 1/8
__device__ float g_k[(size_t)BATCH * NH * S_LEN * DH];
__device__ float g_v[(size_t)BATCH * NH * S_LEN * DH];
__device__ float g_attnout[(size_t)BATCH * S_LEN * CCH];     // [b][s][h*64+d]

// ---------------- tf32 helpers ----------------
__device__ __forceinline__ uint32_t f2tf(float x) {
    uint32_t u;
    asm("cvt.rna.tf32.f32 %0, %1;" : "=r"(u) : "f"(x));
    return u;
}

__device__ __forceinline__ void mma8(float d[4], const uint32_t a[4], const uint32_t b[2]) {
    asm volatile(
        "mma.sync.aligned.m16n8k8.row.col.f32.tf32.tf32.f32 "
        "{%0,%1,%2,%3}, {%4,%5,%6,%7}, {%8,%9}, {%0,%1,%2,%3};\n"
        : "+f"(d[0]), "+f"(d[1]), "+f"(d[2]), "+f"(d[3])
        : "r"(a[0]), "r"(a[1]), "r"(a[2]), "r"(a[3]), "r"(b[0]), "r"(b[1]));
}

// ============================================================
// Kernel 1: QKV projections.
//   A (m=s, k=c) = x_or_ctx[b][c][s]   (s contiguous -> coalesced)
//   B (n=e, k=c) = W[e][c]             (row-major [N,K] == col-major B)
//   out: g_{q,k,v}[(b*8+h)][s][d], q pre-scaled by 0.125 (folds SCALE)
// ============================================================
__global__ __launch_bounds__(256) void qkv_kernel(
    const float* __restrict__ x, const float* __restrict__ ctx,
    const float* __restrict__ Wq, const float* __restrict__ bq,
    const float* __restrict__ Wk, const float* __restrict__ bk,
    const float* __restrict__ Wv, const float* __restrict__ bv)
{
    const int proj = blockIdx.z >> 1;   // 0=Q, 1=K, 2=V
    const int b    = blockIdx.z & 1;
    const float* A    = (proj == 0) ? x  : ctx;
    const float* W    = (proj == 0) ? Wq : (proj == 1) ? Wk : Wv;
    const float* bias = (proj == 0) ? bq : (proj == 1) ? bk : bv;
    float* outbuf     = (proj == 0) ? g_q : (proj == 1) ? g_k : g_v;
    const float scale = (proj == 0) ? 0.125f : 1.0f;

    const int s0 = blockIdx.y * 128;
    const int n0 = blockIdx.x * 128;

    __shared__ float As[16][132];   // tf32 bit patterns, [k][m], pad->conflict-free frags
    __shared__ float Bs[16][132];   // [k][n]

    const int tid  = threadIdx.x;
    const int lane = tid & 31;
    const int warp = tid >> 5;
    const int wm   = warp >> 2;     // 0..1 : 64 rows each
    const int wn   = warp & 3;      // 0..3 : 32 cols each
    const int lr   = lane >> 2;     // 0..7
    const int lc   = lane & 3;      // 0..3

    float acc[4][4][4];
    #pragma unroll
    for (int i = 0; i < 4; i++)
        #pragma unroll
        for (int j = 0; j < 4; j++)
            #pragma unroll
            for (int k = 0; k < 4; k++) acc[i][j][k] = 0.f;

    const float* Ab = A + (size_t)b * CCH * S_LEN;

    for (int kb = 0; kb < CCH; kb += 16) {
        // A tile: 128(m) x 16(k); global: s contiguous per c
        #pragma unroll
        for (int i = 0; i < 8; i++) {
            int idx = tid + i * 256;
            int m = idx & 127, k = idx >> 7;
            As[k][m] = __uint_as_float(f2tf(Ab[(size_t)(kb + k) * S_LEN + s0 + m]));
        }
        // B tile: 128(n) x 16(k) via float4
        #pragma unroll
        for (int i = 0; i < 2; i++) {
            int idx = tid + i * 256;
            int k4 = idx & 3, n = idx >> 2;
            float4 v = *(const float4*)(W + (size_t)(n0 + n) * CCH + kb + k4 * 4);
            Bs[k4 * 4 + 0][n] = __uint_as_float(f2tf(v.x));
            Bs[k4 * 4 + 1][n] = __uint_as_float(f2tf(v.y));
            Bs[k4 * 4 + 2][n] = __uint_as_float(f2tf(v.z));
            Bs[k4 * 4 + 3][n] = __uint_as_float(f2tf(v.w));
        }
        __syncthreads();

        #pragma unroll
        for (int kk = 0; kk < 16; kk += 8) {
            uint32_t af[4][4];
            #pragma unroll
            for (int mt = 0; mt < 4; mt++) {
                int r = wm * 64 + mt * 16 + lr;
                af[mt][0] = __float_as_uint(As[kk + lc][r]);
                af[mt][1] = __float_as_uint(As[kk + lc][r + 8]);
                af[mt][2] = __float_as_uint(As[kk + 4 + lc][r]);
                af[mt][3] = __float_as_uint(As[kk + 4 + lc][r + 8]);
            }
            uint32_t bf[4][2];
            #pragma unroll
            for (int nt = 0; nt < 4; nt++) {
                int c = wn * 32 + nt * 8 + lr;
                bf[nt][0] = __float_as_uint(Bs[kk + lc][c]);
                bf[nt][1] = __float_as_uint(Bs[kk + 4 + lc][c]);
            }
            #pragma unroll
            for (int mt = 0; mt < 4; mt++)
                #pragma unroll
                for (int nt = 0; nt < 4; nt++)
                    mma8(acc[mt][nt], af[mt], bf[nt]);
        }
        __syncthreads();
    }

    // Epilogue: +bias, *scale, store to [bh][s][d]
    #pragma unroll
    for (int mt = 0; mt < 4; mt++) {
        #pragma unroll
        for (int nt = 0; nt < 4; nt++) {
            int r = s0 + wm * 64 + mt * 16 + lr;
            int c = n0 + wn * 32 + nt * 8 + 2 * lc;
            float b0 = bias[c], b1 = bias[c + 1];
            int h = c >> 6, d = c & 63;
            float* obase = outbuf + (((size_t)(b * NH + h)) * S_LEN) * DH + d;
            float2 v0 = make_float2((acc[mt][nt][0] + b0) * scale, (acc[mt][nt][1] + b1) * scale);
            float2 v1 = make_float2((acc[mt][nt][2] + b0) * scale, (acc[mt][nt][3] + b1) * scale);
            *(float2*)(obase + (size_t)r * DH)       = v0;
            *(float2*)(obase + (size_t)(r + 8) * DH) = v1;
        }
    }
}

// ============================================================
// Kernel 2: flash attention. Br=128 q rows / block (8 warps x 16 rows),
// Bc=64 keys per iter, online softmax in fp32, tf32 MMAs.
// smem holds tf32 bit patterns; P re-fragmented through smem for PV.
// ============================================================
#define LD2 68
__global__ __launch_bounds__(256) void attn_kernel()
{
    extern __shared__ float sm[];
    float* Qs = sm;                   // 128 x 68
    float* Ps = sm + 128 * LD2;       // 128 x 68
    float* Ks = sm + 256 * LD2;       // 64 x 68
    float* Vs = sm + 320 * LD2;       // 64 x 68

    const int qt   = blockIdx.x;      // 0..31
    const int bh   = blockIdx.y;      // 0..15
    const int tid  = threadIdx.x;
    const int lane = tid & 31, warp = tid >> 5;
    const int lr   = lane >> 2, lc = lane & 3;

    const float* Qg = g_q + (size_t)bh * S_LEN * DH + (size_t)qt * 128 * DH;
    const float* Kg = g_k + (size_t)bh * S_LEN * DH;
    const float* Vg = g_v + (size_t)bh * S_LEN * DH;

    // Load Q tile once (convert to tf32 bits)
    #pragma unroll
    for (int i = 0; i < 8; i++) {
        int idx = tid + i * 256;      // 0..2047 float4s
        int j = idx >> 4, d4 = idx & 15;
        float4 v = ((const float4*)Qg)[idx];
        float* dst = Qs + j * LD2 + d4 * 4;
        dst[0] = __uint_as_float(f2tf(v.x));
        dst[1] = __uint_as_float(f2tf(v.y));
        dst[2] = __uint_as_float(f2tf(v.z));
        dst[3] = __uint_as_float(f2tf(v.w));
    }

    float o[8][4];
    #pragma unroll
    for (int i = 0; i < 8; i++)
        #pragma unroll
        for (int j = 0; j < 4; j++) o[i][j] = 0.f;
    float m0 = -1e30f, m1 = -1e30f, l0 = 0.f, l1 = 0.f;
    const int rbase = warp * 16;

    for (int jt = 0; jt < 64; jt++) {
        __syncthreads();   // protect Ks/Vs from previous iteration's readers
        const float4* K4 = (const float4*)(Kg + (size_t)jt * 64 * DH);
        const float4* V4 = (const float4*)(Vg + (size_t)jt * 64 * DH);
        #pragma unroll
        for (int i = 0; i < 4; i++) {
            int idx = tid + i * 256;  // 0..1023 float4s
            int j = idx >> 4, d4 = idx & 15;
            float4 kv = K4[idx];
            float* kd = Ks + j * LD2 + d4 * 4;
            kd[0] = __uint_as_float(f2tf(kv.x));
            kd[1] = __uint_as_float(f2tf(kv.y));
            kd[2] = __uint_as_float(f2tf(kv.z));
            kd[3] = __uint_as_float(f2tf(kv.w));
            float4 vv = V4[idx];
            float* vd = Vs + j * LD2 + d4 * 4;
            vd[0] = __uint_as_float(f2tf(vv.x));
            vd[1] = __uint_as_float(f2tf(vv.y));
            vd[2] = __uint_as_float(f2tf(vv.z));
            vd[3] = __uint_as_float(f2tf(vv.w));
        }
        __syncthreads();

        // S = Q Kt (Q pre-scaled), 16x64 per warp
        float s[8][4];
        #pragma unroll
        for (int i = 0; i < 8; i++)
            #pragma unroll
            for (int j2 = 0; j2 < 4; j2++) s[i][j2] = 0.f;

        #pragma unroll
        for (int kk = 0; kk < 64; kk += 8) {
            uint32_t a[4];
            a[0] = __float_as_uint(Qs[(rbase + lr) * LD2 + kk + lc]);
            a[1] = __float_as_uint(Qs[(rbase + lr + 8) * LD2 + kk + lc]);
            a[2] = __float_as_uint(Qs[(rbase + lr) * LD2 + kk + 4 + lc]);
            a[3] = __float_as_uint(Qs[(rbase + lr + 8) * LD2 + kk + 4 + lc]);
            #pragma unroll
            for (int nt = 0; nt < 8; nt++) {
                uint32_t bb[2];
                bb[0] = __float_as_uint(Ks[(nt * 8 + lr) * LD2 + kk + lc]);
                bb[1] = __float_as_uint(Ks[(nt * 8 + lr) * LD2 + kk + 4 + lc]);
                mma8(s[nt], a, bb);
            }
        }

        // Online softmax: rows r0 = rbase+lr (regs 0,1), r1 = r0+8 (regs 2,3)
        float mx0 = s[0][0], mx1 = s[0][2];
        #pragma unroll
        for (int nt = 0; nt < 8; nt++) {
            mx0 = fmaxf(mx0, fmaxf(s[nt][0], s[nt][1]));
            mx1 = fmaxf(mx1, fmaxf(s[nt][2], s[nt][3]));
        }
        mx0 = fmaxf(mx0, __shfl_xor_sync(0xffffffffu, mx0, 1));
        mx0 = fmaxf(mx0, __shfl_xor_sync(0xffffffffu, mx0, 2));
        mx1 = fmaxf(mx1, __shfl_xor_sync(0xffffffffu, mx1, 1));
        mx1 = fmaxf(mx1, __shfl_xor_sync(0xffffffffu, mx1, 2));
        float mn0 = fmaxf(m0, mx0), mn1 = fmaxf(m1, mx1);
        float f0 = __expf(m0 - mn0), f1 = __expf(m1 - mn1);
        float sum0 = 0.f, sum1 = 0.f;
        #pragma unroll
        for (int nt = 0; nt < 8; nt++) {
            s[nt][0] = __expf(s[nt][0] - mn0); sum0 += s[nt][0];
            s[nt][1] = __expf(s[nt][1] - mn0); sum0 += s[nt][1];
            s[nt][2] = __expf(s[nt][2] - mn1); sum1 += s[nt][2];
            s[nt][3] = __expf(s[nt][3] - mn1); sum1 += s[nt][3];
        }
        sum0 += __shfl_xor_sync(0xffffffffu, sum0, 1);
        sum0 += __shfl_xor_sync(0xffffffffu, sum0, 2);
        sum1 += __shfl_xor_sync(0xffffffffu, sum1, 1);
        sum1 += __shfl_xor_sync(0xffffffffu, sum1, 2);
        l0 = l0 * f0 + sum0;
        l1 = l1 * f1 + sum1;
        m0 = mn0; m1 = mn1;
        #pragma unroll
        for (int dt = 0; dt < 8; dt++) {
            o[dt][0] *= f0; o[dt][1] *= f0; o[dt][2] *= f1; o[dt][3] *= f1;
        }

        // Write P (tf32 bits) to smem to re-fragment as MMA-A for PV
        const int r0 = rbase + lr, r1 = r0 + 8;
        #pragma unroll
        for (int nt = 0; nt < 8; nt++) {
            int c = nt * 8 + 2 * lc;
            *(float2*)(Ps + r0 * LD2 + c) =
                make_float2(__uint_as_float(f2tf(s[nt][0])), __uint_as_float(f2tf(s[nt][1])));
            *(float2*)(Ps + r1 * LD2 + c) =
                make_float2(__uint_as_float(f2tf(s[nt][2])), __uint_as_float(f2tf(s[nt][3])));
        }
        __syncwarp();   // each warp reads only its own 16 P-rows

        // O += P V  (contraction over j; B(k=j, n=d) = Vs[j][d])
        #pragma unroll
        for (int kk = 0; kk < 64; kk += 8) {
            uint32_t a[4];
            a[0] = __float_as_uint(Ps[(rbase + lr) * LD2 + kk + lc]);
            a[1] = __float_as_uint(Ps[(rbase + lr + 8) * LD2 + kk + lc]);
            a[2] = __float_as_uint(Ps[(rbase + lr) * LD2 + kk + 4 + lc]);
            a[3] = __float_as_uint(Ps[(rbase + lr + 8) * LD2 + kk + 4 + lc]);
            #pragma unroll
            for (int dt = 0; dt < 8; dt++) {
                uint32_t bb[2];
                bb[0] = __float_as_uint(Vs[(kk + lc) * LD2 + dt * 8 + lr]);
                bb[1] = __float_as_uint(Vs[(kk + 4 + lc) * LD2 + dt * 8 + lr]);
                mma8(o[dt], a, bb);
            }
        }
    }

    // Epilogue: normalize, store to g_attnout[b][s][h*64+d]
    float inv0 = 1.f / l0, inv1 = 1.f / l1;
    const int b = bh >> 3, h = bh & 7;
    const int srow0 = qt * 128 + rbase + lr;
    float* obase = g_attnout + (size_t)b * S_LEN * CCH + (size_t)h * DH;
    #pragma unroll
    for (int dt = 0; dt < 8; dt++) {
        int d = dt * 8 + 2 * lc;
        *(float2*)(obase + (size_t)srow0 * CCH + d) =
            make_float2(o[dt][0] * inv0, o[dt][1] * inv0);
        *(float2*)(obase + (size_t)(srow0 + 8) * CCH + d) =
            make_float2(o[dt][2] * inv1, o[dt][3] * inv1);
    }
}

// ============================================================
// Kernel 3: output projection + transpose store to [b][c][s].
//   A (m=b*4096+s, k=e) = g_attnout  (row-major)
//   B (n=c, k=e)        = Wo[c][e]
// ============================================================
__global__ __launch_bounds__(256) void oproj_kernel(
    const float* __restrict__ Wo, const float* __restrict__ bo, float* __restrict__ out)
{
    const int m0 = blockIdx.y * 128;   // over 8192
    const int n0 = blockIdx.x * 128;   // over 512

    __shared__ float As[16][132];
    __shared__ float Bs[16][132];

    const int tid  = threadIdx.x;
    const int lane = tid & 31;
    const int warp = tid >> 5;
    const int wm   = warp >> 2;
    const int wn   = warp & 3;
    const int lr   = lane >> 2;
    const int lc   = lane & 3;

    float acc[4][4][4];
    #pragma unroll
    for (int i = 0; i < 4; i++)
        #pragma unroll
        for (int j = 0; j < 4; j++)
            #pragma unroll
            for (int k = 0; k < 4; k++) acc[i][j][k] = 0.f;

    for (int kb = 0; kb < CCH; kb += 16) {
        #pragma unroll
        for (int i = 0; i < 2; i++) {
            int idx = tid + i * 256;
            int k4 = idx & 3, m = idx >> 2;
            float4 v = *(const float4*)(g_attnout + (size_t)(m0 + m) * CCH + kb + k4 * 4);
            As[k4 * 4 + 0][m] = __uint_as_float(f2tf(v.x));
            As[k4 * 4 + 1][m] = __uint_as_float(f2tf(v.y));
            As[k4 * 4 + 2][m] = __uint_as_float(f2tf(v.z));
            As[k4 * 4 + 3][m] = __uint_as_float(f2tf(v.w));
        }
        #pragma unroll
        for (int i = 0; i < 2; i++) {
            int idx = tid + i * 256;
            int k4 = idx & 3, n = idx >> 2;
            float4 v = *(const float4*)(Wo + (size_t)(n0 + n) * CCH + kb + k4 * 4);
            Bs[k4 * 4 + 0][n] = __uint_as_float(f2tf(v.x));
            Bs[k4 * 4 + 1][n] = __uint_as_float(f2tf(v.y));
            Bs[k4 * 4 + 2][n] = __uint_as_float(f2tf(v.z));
            Bs[k4 * 4 + 3][n] = __uint_as_float(f2tf(v.w));
        }
        __syncthreads();

        #pragma unroll
        for (int kk = 0; kk < 16; kk += 8) {
            uint32_t af[4][4];
            #pragma unroll
            for (int mt = 0; mt < 4; mt++) {
                int r = wm * 64 + mt * 16 + lr;
                af[mt][0] = __float_as_uint(As[kk + lc][r]);
                af[mt][1] = __float_as_uint(As[kk + lc][r + 8]);
                af[mt][2] = __float_as_uint(As[kk + 4 + lc][r]);
                af[mt][3] = __float_as_uint(As[kk + 4 + lc][r + 8]);
            }
            uint32_t bf[4][2];
            #pragma unroll
            for (int nt = 0; nt < 4; nt++) {
                int c = wn * 32 + nt * 8 + lr;
                bf[nt][0] = __float_as_uint(Bs[kk + lc][c]);
                bf[nt][1] = __float_as_uint(Bs[kk + 4 + lc][c]);
            }
            #pragma unroll
            for (int mt = 0; mt < 4; mt++)
                #pragma unroll
                for (int nt = 0; nt < 4; nt++)
                    mma8(acc[mt][nt], af[mt], bf[nt]);
        }
        __syncthreads();
    }

    // Epilogue: +bias, transposed store out[b][c][s]
    #pragma unroll
    for (int mt = 0; mt < 4; mt++) {
        #pragma unroll
        for (int nt = 0; nt < 4; nt++) {
            int r = m0 + wm * 64 + mt * 16 + lr;     // global row = b*4096 + s
            int c = n0 + wn * 32 + nt * 8 + 2 * lc;  // out channel
            int bb = r >> 12, ss = r & 4095;
            float bias0 = bo[c], bias1 = bo[c + 1];
            float* pc  = out + ((size_t)bb * CCH + c) * S_LEN;
            float* pc1 = pc + S_LEN;
            pc[ss]      = acc[mt][nt][0] + bias0;
            pc1[ss]     = acc[mt][nt][1] + bias1;
            pc[ss + 8]  = acc[mt][nt][2] + bias0;
            pc1[ss + 8] = acc[mt][nt][3] + bias1;
        }
    }
}

// ============================================================
extern "C" void kernel_launch(void* const* d_in, const int* in_sizes, int n_in,
                              void* d_out, int out_size)
{
    const float* x   = (const float*)d_in[0];
    const float* ctx = (const float*)d_in[1];
    const float* Wq  = (const float*)d_in[2];
    const float* bq  = (const float*)d_in[3];
    const float* Wk  = (const float*)d_in[4];
    const float* bk  = (const float*)d_in[5];
    const float* Wv  = (const float*)d_in[6];
    const float* bv  = (const float*)d_in[7];
    const float* Wo  = (const float*)d_in[8];
    const float* bo  = (const float*)d_in[9];
    float* out = (float*)d_out;

    const int SMEM2 = 384 * LD2 * 4;  // 104448 B: Q(128)+P(128)+K(64)+V(64) rows x 68
    cudaFuncSetAttribute(attn_kernel, cudaFuncAttributeMaxDynamicSharedMemorySize, SMEM2);

    qkv_kernel<<<dim3(4, 32, 6), 256>>>(x, ctx, Wq, bq, Wk, bk, Wv, bv);
    attn_kernel<<<dim3(32, 16), 256, SMEM2>>>();
    oproj_kernel<<<dim3(4, 64), 256>>>(Wo, bo, out);
}

// round 8
// speedup vs baseline: 1.3421x; 1.3421x over previous
#include <cuda_runtime.h>
#include <cstdint>

#define S_LEN 4096
#define CCH   512
#define NH    8
#define DH    64
#define BATCH 2

// Scratch: g_q/g_k/g_v hold tf32 BIT PATTERNS (converted in qkv epilogue).
__device__ float g_q[(size_t)BATCH * NH * S_LEN * DH];   // pre-scaled by 1/8
__device__ float g_k[(size_t)BATCH * NH * S_LEN * DH];
__device__ float g_v[(size_t)BATCH * NH * S_LEN * DH];
__device__ float g_attnout[(size_t)BATCH * S_LEN * CCH]; // fp32

__device__ __forceinline__ uint32_t f2tf(float x) {
    uint32_t u; asm("cvt.rna.tf32.f32 %0, %1;" : "=r"(u) : "f"(x)); return u;
}
__device__ __forceinline__ float f2tff(float x) { return __uint_as_float(f2tf(x)); }

__device__ __forceinline__ void mma8(float d[4], const uint32_t a[4], const uint32_t b[2]) {
    asm volatile(
        "mma.sync.aligned.m16n8k8.row.col.f32.tf32.tf32.f32 "
        "{%0,%1,%2,%3}, {%4,%5,%6,%7}, {%8,%9}, {%0,%1,%2,%3};\n"
        : "+f"(d[0]), "+f"(d[1]), "+f"(d[2]), "+f"(d[3])
        : "r"(a[0]), "r"(a[1]), "r"(a[2]), "r"(a[3]), "r"(b[0]), "r"(b[1]));
}
__device__ __forceinline__ void cp_async16(uint32_t s, const void* g) {
    asm volatile("cp.async.cg.shared.global [%0], [%1], 16;\n" :: "r"(s), "l"(g));
}
__device__ __forceinline__ void cp_commit() { asm volatile("cp.async.commit_group;\n"); }
template<int N> __device__ __forceinline__ void cp_wait() {
    asm volatile("cp.async.wait_group %0;\n" :: "n"(N));
}

// ============================================================
// Kernel 1: QKV projections (epilogue stores tf32 bits)
// ============================================================
__global__ __launch_bounds__(256) void qkv_kernel(
    const float* __restrict__ x, const float* __restrict__ ctx,
    const float* __restrict__ Wq, const float* __restrict__ bq,
    const float* __restrict__ Wk, const float* __restrict__ bk,
    const float* __restrict__ Wv, const float* __restrict__ bv)
{
    const int proj = blockIdx.z >> 1;
    const int b    = blockIdx.z & 1;
    const float* A    = (proj == 0) ? x  : ctx;
    const float* W    = (proj == 0) ? Wq : (proj == 1) ? Wk : Wv;
    const float* bias = (proj == 0) ? bq : (proj == 1) ? bk : bv;
    float* outbuf     = (proj == 0) ? g_q : (proj == 1) ? g_k : g_v;
    const float scale = (proj == 0) ? 0.125f : 1.0f;

    const int s0 = blockIdx.y * 128;
    const int n0 = blockIdx.x * 128;

    __shared__ float As[16][136];   // 136%32==8 -> conflict-free frag loads
    __shared__ float Bs[16][136];

    const int tid = threadIdx.x, lane = tid & 31, warp = tid >> 5;
    const int wm = warp >> 2, wn = warp & 3, lr = lane >> 2, lc = lane & 3;

    float acc[4][4][4];
    #pragma unroll
    for (int i = 0; i < 4; i++)
        #pragma unroll
        for (int j = 0; j < 4; j++)
            #pragma unroll
            for (int k = 0; k < 4; k++) acc[i][j][k] = 0.f;

    const float* Ab = A + (size_t)b * CCH * S_LEN;

    for (int kb = 0; kb < CCH; kb += 16) {
        #pragma unroll
        for (int i = 0; i < 8; i++) {
            int idx = tid + i * 256;
            int m = idx & 127, k = idx >> 7;
            As[k][m] = f2tff(Ab[(size_t)(kb + k) * S_LEN + s0 + m]);
        }
        #pragma unroll
        for (int i = 0; i < 2; i++) {
            int idx = tid + i * 256;
            int k4 = idx & 3, n = idx >> 2;
            float4 v = *(const float4*)(W + (size_t)(n0 + n) * CCH + kb + k4 * 4);
            Bs[k4 * 4 + 0][n] = f2tff(v.x);
            Bs[k4 * 4 + 1][n] = f2tff(v.y);
            Bs[k4 * 4 + 2][n] = f2tff(v.z);
            Bs[k4 * 4 + 3][n] = f2tff(v.w);
        }
        __syncthreads();

        #pragma unroll
        for (int kk = 0; kk < 16; kk += 8) {
            uint32_t af[4][4];
            #pragma unroll
            for (int mt = 0; mt < 4; mt++) {
                int r = wm * 64 + mt * 16 + lr;
                af[mt][0] = __float_as_uint(As[kk + lc][r]);
                af[mt][1] = __float_as_uint(As[kk + lc][r + 8]);
                af[mt][2] = __float_as_uint(As[kk + 4 + lc][r]);
                af[mt][3] = __float_as_uint(As[kk + 4 + lc][r + 8]);
            }
            uint32_t bf[4][2];
            #pragma unroll
            for (int nt = 0; nt < 4; nt++) {
                int c = wn * 32 + nt * 8 + lr;
                bf[nt][0] = __float_as_uint(Bs[kk + lc][c]);
                bf[nt][1] = __float_as_uint(Bs[kk + 4 + lc][c]);
            }
            #pragma unroll
            for (int mt = 0; mt < 4; mt++)
                #pragma unroll
                for (int nt = 0; nt < 4; nt++)
                    mma8(acc[mt][nt], af[mt], bf[nt]);
        }
        __syncthreads();
    }

    #pragma unroll
    for (int mt = 0; mt < 4; mt++) {
        #pragma unroll
        for (int nt = 0; nt < 4; nt++) {
            int r = s0 + wm * 64 + mt * 16 + lr;
            int c = n0 + wn * 32 + nt * 8 + 2 * lc;
            float b0 = bias[c], b1 = bias[c + 1];
            int h = c >> 6, d = c & 63;
            float* obase = outbuf + (((size_t)(b * NH + h)) * S_LEN) * DH + d;
            *(float2*)(obase + (size_t)r * DH) = make_float2(
                f2tff((acc[mt][nt][0] + b0) * scale), f2tff((acc[mt][nt][1] + b1) * scale));
            *(float2*)(obase + (size_t)(r + 8) * DH) = make_float2(
                f2tff((acc[mt][nt][2] + b0) * scale), f2tff((acc[mt][nt][3] + b1) * scale));
        }
    }
}

// ============================================================
// Kernel 2: flash attention. Q frags in regs, cp.async double-buffered K/V,
// P->A frags via shuffles. K stride 68, V stride 72 (both conflict-free).
// smem floats: Q[128*68] | K0[64*68] K1[64*68] | V0[64*72] V1[64*72]
// ============================================================
#define QF_  (128 * 68)
#define KOFF(p) (QF_ + (p) * (64 * 68))
#define VOFF(p) (QF_ + 2 * 64 * 68 + (p) * (64 * 72))
#define SMEMA ((QF_ + 2 * 64 * 68 + 2 * 64 * 72) * 4)

__device__ __forceinline__ void fill_kv(uint32_t smb, const float* Kg, const float* Vg,
                                        int jt, int p, int tid)
{
    const float* K4 = Kg + (size_t)jt * 64 * DH;
    const float* V4 = Vg + (size_t)jt * 64 * DH;
    uint32_t kb = smb + KOFF(p) * 4;
    uint32_t vb = smb + VOFF(p) * 4;
    #pragma unroll
    for (int i = 0; i < 4; i++) {
        int idx = tid + i * 256;
        int j = idx >> 4, c4 = idx & 15;
        cp_async16(kb + (uint32_t)(j * 68 + c4 * 4) * 4, K4 + j * DH + c4 * 4);
        cp_async16(vb + (uint32_t)(j * 72 + c4 * 4) * 4, V4 + j * DH + c4 * 4);
    }
}

__global__ __launch_bounds__(256) void attn_kernel()
{
    extern __shared__ float sm[];
    const int qt = blockIdx.x, bh = blockIdx.y;
    const int tid = threadIdx.x, lane = tid & 31, warp = tid >> 5;
    const int lr = lane >> 2, lc = lane & 3;
    const int rbase = warp * 16;

    const float* Qg = g_q + (size_t)bh * S_LEN * DH + (size_t)qt * 128 * DH;
    const float* Kg = g_k + (size_t)bh * S_LEN * DH;
    const float* Vg = g_v + (size_t)bh * S_LEN * DH;

    uint32_t smb = (uint32_t)__cvta_generic_to_shared(sm);

    // Q fill (group 0): pure copy, bits already tf32
    #pragma unroll
    for (int i = 0; i < 8; i++) {
        int idx = tid + i * 256;
        int j = idx >> 4, c4 = idx & 15;
        cp_async16(smb + (uint32_t)(j * 68 + c4 * 4) * 4, Qg + j * DH + c4 * 4);
    }
    cp_commit();
    fill_kv(smb, Kg, Vg, 0, 0, tid);
    cp_commit();
    cp_wait<1>();
    __syncthreads();

    // Q fragments -> registers, never re-read
    uint32_t qf[8][4];
    #pragma unroll
    for (int kt = 0; kt < 8; kt++) {
        int r = rbase + lr;
        qf[kt][0] = __float_as_uint(sm[r * 68 + kt * 8 + lc]);
        qf[kt][1] = __float_as_uint(sm[(r + 8) * 68 + kt * 8 + lc]);
        qf[kt][2] = __float_as_uint(sm[r * 68 + kt * 8 + 4 + lc]);
        qf[kt][3] = __float_as_uint(sm[(r + 8) * 68 + kt * 8 + 4 + lc]);
    }

    float o[8][4];
    #pragma unroll
    for (int i = 0; i < 8; i++)
        #pragma unroll
        for (int j = 0; j < 4; j++) o[i][j] = 0.f;
    float m0 = -1e30f, m1 = -1e30f, l0 = 0.f, l1 = 0.f;

    const int srcA = (lane & 28) | (lc >> 1);
    const int srcB = srcA + 2;
    const bool odd = lc & 1;

    for (int jt = 0; jt < 64; jt++) {
        const int p = jt & 1;
        __syncthreads();                       // prev compute done before refilling p^1
        if (jt < 63) { fill_kv(smb, Kg, Vg, jt + 1, p ^ 1, tid); cp_commit(); cp_wait<1>(); }
        else         { cp_wait<0>(); }
        __syncthreads();                       // fill(jt) visible to all

        const float* Ksb = sm + KOFF(p);
        const float* Vsb = sm + VOFF(p);

        // S = Q K^T
        float s[8][4];
        #pragma unroll
        for (int i = 0; i < 8; i++)
            #pragma unroll
            for (int j2 = 0; j2 < 4; j2++) s[i][j2] = 0.f;

        #pragma unroll
        for (int kt = 0; kt < 8; kt++) {
            #pragma unroll
            for (int nt = 0; nt < 8; nt++) {
                uint32_t bb[2];
                bb[0] = __float_as_uint(Ksb[(nt * 8 + lr) * 68 + kt * 8 + lc]);
                bb[1] = __float_as_uint(Ksb[(nt * 8 + lr) * 68 + kt * 8 + 4 + lc]);
                mma8(s[nt], qf[kt], bb);
            }
        }

        // Online softmax (identical statement order to prior rounds)
        float mx0 = s[0][0], mx1 = s[0][2];
        #pragma unroll
        for (int nt = 0; nt < 8; nt++) {
            mx0 = fmaxf(mx0, fmaxf(s[nt][0], s[nt][1]));
            mx1 = fmaxf(mx1, fmaxf(s[nt][2], s[nt][3]));
        }
        mx0 = fmaxf(mx0, __shfl_xor_sync(0xffffffffu, mx0, 1));
        mx0 = fmaxf(mx0, __shfl_xor_sync(0xffffffffu, mx0, 2));
        mx1 = fmaxf(mx1, __shfl_xor_sync(0xffffffffu, mx1, 1));
        mx1 = fmaxf(mx1, __shfl_xor_sync(0xffffffffu, mx1, 2));
        float mn0 = fmaxf(m0, mx0), mn1 = fmaxf(m1, mx1);
        float f0 = __expf(m0 - mn0), f1 = __expf(m1 - mn1);
        float sum0 = 0.f, sum1 = 0.f;
        #pragma unroll
        for (int nt = 0; nt < 8; nt++) {
            s[nt][0] = __expf(s[nt][0] - mn0); sum0 += s[nt][0];
            s[nt][1] = __expf(s[nt][1] - mn0); sum0 += s[nt][1];
            s[nt][2] = __expf(s[nt][2] - mn1); sum1 += s[nt][2];
            s[nt][3] = __expf(s[nt][3] - mn1); sum1 += s[nt][3];
        }
        sum0 += __shfl_xor_sync(0xffffffffu, sum0, 1);
        sum0 += __shfl_xor_sync(0xffffffffu, sum0, 2);
        sum1 += __shfl_xor_sync(0xffffffffu, sum1, 1);
        sum1 += __shfl_xor_sync(0xffffffffu, sum1, 2);
        l0 = l0 * f0 + sum0;
        l1 = l1 * f1 + sum1;
        m0 = mn0; m1 = mn1;
        #pragma unroll
        for (int dt = 0; dt < 8; dt++) {
            o[dt][0] *= f0; o[dt][1] *= f0; o[dt][2] *= f1; o[dt][3] *= f1;
        }

        // Convert P to tf32 bits in place (after fp32 sums — identical numerics)
        #pragma unroll
        for (int nt = 0; nt < 8; nt++)
            #pragma unroll
            for (int e = 0; e < 4; e++) s[nt][e] = f2tff(s[nt][e]);

        // O += P V : A-fragments via shuffles (no smem round-trip)
        #pragma unroll
        for (int kt = 0; kt < 8; kt++) {
            float u0 = __shfl_sync(0xffffffffu, s[kt][0], srcA);
            float u1 = __shfl_sync(0xffffffffu, s[kt][1], srcA);
            float u2 = __shfl_sync(0xffffffffu, s[kt][2], srcA);
            float u3 = __shfl_sync(0xffffffffu, s[kt][3], srcA);
            float w0 = __shfl_sync(0xffffffffu, s[kt][0], srcB);
            float w1 = __shfl_sync(0xffffffffu, s[kt][1], srcB);
            float w2 = __shfl_sync(0xffffffffu, s[kt][2], srcB);
            float w3 = __shfl_sync(0xffffffffu, s[kt][3], srcB);
            uint32_t a[4];
            a[0] = __float_as_uint(odd ? u1 : u0);
            a[1] = __float_as_uint(odd ? u3 : u2);
            a[2] = __float_as_uint(odd ? w1 : w0);
            a[3] = __float_as_uint(odd ? w3 : w2);
            #pragma unroll
            for (int dt = 0; dt < 8; dt++) {
                uint32_t bb[2];
                bb[0] = __float_as_uint(Vsb[(kt * 8 + lc) * 72 + dt * 8 + lr]);
                bb[1] = __float_as_uint(Vsb[(kt * 8 + 4 + lc) * 72 + dt * 8 + lr]);
                mma8(o[dt], a, bb);
            }
        }
    }

    float inv0 = 1.f / l0, inv1 = 1.f / l1;
    const int b = bh >> 3, h = bh & 7;
    const int srow0 = qt * 128 + rbase + lr;
    float* obase = g_attnout + (size_t)b * S_LEN * CCH + (size_t)h * DH;
    #pragma unroll
    for (int dt = 0; dt < 8; dt++) {
        int d = dt * 8 + 2 * lc;
        *(float2*)(obase + (size_t)srow0 * CCH + d) =
            make_float2(o[dt][0] * inv0, o[dt][1] * inv0);
        *(float2*)(obase + (size_t)(srow0 + 8) * CCH + d) =
            make_float2(o[dt][2] * inv1, o[dt][3] * inv1);
    }
}

// ============================================================
// Kernel 3: output projection + transpose store to [b][c][s]
// ============================================================
__global__ __launch_bounds__(256) void oproj_kernel(
    const float* __restrict__ Wo, const float* __restrict__ bo, float* __restrict__ out)
{
    const int m0 = blockIdx.y * 128;
    const int n0 = blockIdx.x * 128;

    __shared__ float As[16][136];
    __shared__ float Bs[16][136];

    const int tid = threadIdx.x, lane = tid & 31, warp = tid >> 5;
    const int wm = warp >> 2, wn = warp & 3, lr = lane >> 2, lc = lane & 3;

    float acc[4][4][4];
    #pragma unroll
    for (int i = 0; i < 4; i++)
        #pragma unroll
        for (int j = 0; j < 4; j++)
            #pragma unroll
            for (int k = 0; k < 4; k++) acc[i][j][k] = 0.f;

    for (int kb = 0; kb < CCH; kb += 16) {
        #pragma unroll
        for (int i = 0; i < 2; i++) {
            int idx = tid + i * 256;
            int k4 = idx & 3, m = idx >> 2;
            float4 v = *(const float4*)(g_attnout + (size_t)(m0 + m) * CCH + kb + k4 * 4);
            As[k4 * 4 + 0][m] = f2tff(v.x);
            As[k4 * 4 + 1][m] = f2tff(v.y);
            As[k4 * 4 + 2][m] = f2tff(v.z);
            As[k4 * 4 + 3][m] = f2tff(v.w);
        }
        #pragma unroll
        for (int i = 0; i < 2; i++) {
            int idx = tid + i * 256;
            int k4 = idx & 3, n = idx >> 2;
            float4 v = *(const float4*)(Wo + (size_t)(n0 + n) * CCH + kb + k4 * 4);
            Bs[k4 * 4 + 0][n] = f2tff(v.x);
            Bs[k4 * 4 + 1][n] = f2tff(v.y);
            Bs[k4 * 4 + 2][n] = f2tff(v.z);
            Bs[k4 * 4 + 3][n] = f2tff(v.w);
        }
        __syncthreads();

        #pragma unroll
        for (int kk = 0; kk < 16; kk += 8) {
            uint32_t af[4][4];
            #pragma unroll
            for (int mt = 0; mt < 4; mt++) {
                int r = wm * 64 + mt * 16 + lr;
                af[mt][0] = __float_as_uint(As[kk + lc][r]);
                af[mt][1] = __float_as_uint(As[kk + lc][r + 8]);
                af[mt][2] = __float_as_uint(As[kk + 4 + lc][r]);
                af[mt][3] = __float_as_uint(As[kk + 4 + lc][r + 8]);
            }
            uint32_t bf[4][2];
            #pragma unroll
            for (int nt = 0; nt < 4; nt++) {
                int c = wn * 32 + nt * 8 + lr;
                bf[nt][0] = __float_as_uint(Bs[kk + lc][c]);
                bf[nt][1] = __float_as_uint(Bs[kk + 4 + lc][c]);
            }
            #pragma unroll
            for (int mt = 0; mt < 4; mt++)
                #pragma unroll
                for (int nt = 0; nt < 4; nt++)
                    mma8(acc[mt][nt], af[mt], bf[nt]);
        }
        __syncthreads();
    }

    #pragma unroll
    for (int mt = 0; mt < 4; mt++) {
        #pragma unroll
        for (int nt = 0; nt < 4; nt++) {
            int r = m0 + wm * 64 + mt * 16 + lr;
            int c = n0 + wn * 32 + nt * 8 + 2 * lc;
            int bb = r >> 12, ss = r & 4095;
            float bias0 = bo[c], bias1 = bo[c + 1];
            float* pc  = out + ((size_t)bb * CCH + c) * S_LEN;
            float* pc1 = pc + S_LEN;
            pc[ss]      = acc[mt][nt][0] + bias0;
            pc1[ss]     = acc[mt][nt][1] + bias1;
            pc[ss + 8]  = acc[mt][nt][2] + bias0;
            pc1[ss + 8] = acc[mt][nt][3] + bias1;
        }
    }
}

// ============================================================
extern "C" void kernel_launch(void* const* d_in, const int* in_sizes, int n_in,
                              void* d_out, int out_size)
{
    const float* x   = (const float*)d_in[0];
    const float* ctx = (const float*)d_in[1];
    const float* Wq  = (const float*)d_in[2];
    const float* bq  = (const float*)d_in[3];
    const float* Wk  = (const float*)d_in[4];
    const float* bk  = (const float*)d_in[5];
    const float* Wv  = (const float*)d_in[6];
    const float* bv  = (const float*)d_in[7];
    const float* Wo  = (const float*)d_in[8];
    const float* bo  = (const float*)d_in[9];
    float* out = (float*)d_out;

    cudaFuncSetAttribute(attn_kernel, cudaFuncAttributeMaxDynamicSharedMemorySize, SMEMA);

    qkv_kernel<<<dim3(4, 32, 6), 256>>>(x, ctx, Wq, bq, Wk, bk, Wv, bv);
    attn_kernel<<<dim3(32, 16), 256, SMEMA>>>();
    oproj_kernel<<<dim3(4, 64), 256>>>(Wo, bo, out);
}